// round 1
// baseline (speedup 1.0000x reference)
#include <cuda_runtime.h>
#include <cuda_bf16.h>

// ContinuousEmbedding: out[b,f,:] = sum_k weight[k,:] / (|idx(x[b,f]) - k| + 1)
// Collapses to a 64x64 lookup table T indexed by bucket index.
//
// Kernel 1: build T[64][64] into a __device__ scratch array.
// Kernel 2: streaming gather-store: for each output float4, compute bucket
//           index of its row's x, copy T row slice from shared memory.

#define NUM_BINS 63
#define KDIM 64          // NUM_BINS + 1
#define EMB_DIM 64

__device__ float g_table[KDIM * EMB_DIM];   // scratch (allocation-free rule)

// ---------------------------------------------------------------------------
// Kernel 1: T[i][d] = sum_k weight[k][d] * (1/(|i-k|+1))
// <<<64, 64>>> — trivial cost (~few us at most, actually well under 1 us)
// ---------------------------------------------------------------------------
__global__ void build_table_kernel(const float* __restrict__ weight) {
    const int i = blockIdx.x;    // target index 0..63
    const int d = threadIdx.x;   // emb dim 0..63
    float acc = 0.0f;
#pragma unroll
    for (int k = 0; k < KDIM; ++k) {
        int diff = i - k; if (diff < 0) diff = -diff;
        float scale = 1.0f / (float)(diff + 1);
        acc = fmaf(weight[k * EMB_DIM + d], scale, acc);
    }
    g_table[i * EMB_DIM + d] = acc;
}

// ---------------------------------------------------------------------------
// Kernel 2: streaming output.
// Each thread handles one float4 of the output (16 B). 16 consecutive threads
// share one row (one x value). Bucket index: arithmetic first guess (bins are
// ~linspace(-3.1, 3.1, 63) with step 0.1) then EXACT fixup against the real
// bin values so semantics match (x > low[i]) && (x <= high[i]) precisely.
// ---------------------------------------------------------------------------
__global__ void __launch_bounds__(256)
embed_kernel(const float* __restrict__ x,
             const float* __restrict__ low,   // [64]; bins = low[1..63]
             float4* __restrict__ out,
             int n_items)                      // total float4 count
{
    __shared__ float4 sT[KDIM * (EMB_DIM / 4)];   // 16 KB table
    __shared__ float  sb[NUM_BINS];               // bin boundaries

    // Cooperative load of the table (as float4) + bins
    const float4* gT4 = reinterpret_cast<const float4*>(g_table);
#pragma unroll
    for (int i = threadIdx.x; i < KDIM * (EMB_DIM / 4); i += 256)
        sT[i] = gT4[i];
    if (threadIdx.x < NUM_BINS)
        sb[threadIdx.x] = low[threadIdx.x + 1];
    __syncthreads();

    const int stride = gridDim.x * blockDim.x;
    for (int gid = blockIdx.x * blockDim.x + threadIdx.x; gid < n_items; gid += stride) {
        const int row  = gid >> 4;       // which (b,f)
        const int part = gid & 15;       // which float4 within the 64-dim row

        const float xv = __ldg(x + row);

        // index = #{ j : bins[j] < x }  (== argmax of the one-hot bucket mask)
        // Arithmetic guess (bins ~ -3.1 + j*0.1), then exact fixup.
        int g = (int)floorf((xv + 3.1f) * 10.0f) + 1;
        g = max(0, min(NUM_BINS, g));
        while (g > 0 && !(xv > sb[g - 1])) --g;          // too high -> step down
        while (g < NUM_BINS && (xv > sb[g])) ++g;        // too low  -> step up

        const float4 v = sT[(g << 4) + part];
        __stcs(out + gid, v);            // streaming store (evict-first)
    }
}

extern "C" void kernel_launch(void* const* d_in, const int* in_sizes, int n_in,
                              void* d_out, int out_size) {
    const float* x      = (const float*)d_in[0];   // [8192*64]
    const float* low    = (const float*)d_in[1];   // [64]
    // d_in[2] = high [64] (redundant with low for bucket computation)
    const float* weight = (const float*)d_in[3];   // [64*64]

    float4* out = (float4*)d_out;
    const int n_items = out_size / 4;              // float4 count

    build_table_kernel<<<KDIM, EMB_DIM>>>(weight);

    const int threads = 256;
    int blocks = 148 * 8;                          // grid-stride; table loaded once/block
    int max_blocks = (n_items + threads - 1) / threads;
    if (blocks > max_blocks) blocks = max_blocks;
    embed_kernel<<<blocks, threads>>>(x, low, out, n_items);
}

// round 2
// speedup vs baseline: 1.2672x; 1.2672x over previous
#include <cuda_runtime.h>
#include <cuda_bf16.h>

// ContinuousEmbedding: out[b,f,:] = sum_k weight[k,:] / (|idx(x[b,f]) - k| + 1)
// Collapses to a 64x64 lookup table T indexed by bucket index.
//
// Kernel 1 (fast): build T[64][64] with weight staged via shared memory.
// Kernel 2: warp-cooperative streaming fan-out. Each lane computes the bucket
//           index for ONE row; shfl distributes indices; 16 unrolled
//           LDS.128+STG.128 per warp-iter write 32 rows (8 KB) coalesced.

#define NUM_BINS 63
#define KDIM 64          // NUM_BINS + 1
#define EMB_DIM 64

__device__ float g_table[KDIM * EMB_DIM];   // scratch (allocation-free rule)

// ---------------------------------------------------------------------------
// Kernel 1: T[i][d] = sum_k weight[k][d] * (1/(|i-k|+1))
// <<<16, 256>>>: block b computes rows 4b..4b+3; weight staged in shared.
// ---------------------------------------------------------------------------
__global__ void __launch_bounds__(256)
build_table_kernel(const float* __restrict__ weight) {
    __shared__ float sw[KDIM * EMB_DIM];          // 16 KB
    float4* sw4 = reinterpret_cast<float4*>(sw);
    const float4* w4 = reinterpret_cast<const float4*>(weight);
#pragma unroll
    for (int i = threadIdx.x; i < KDIM * EMB_DIM / 4; i += 256)
        sw4[i] = w4[i];
    __syncthreads();

    const int r = blockIdx.x * 4 + (threadIdx.x >> 6);  // table row 0..63
    const int d = threadIdx.x & 63;                     // emb dim 0..63
    float acc = 0.0f;
#pragma unroll
    for (int k = 0; k < KDIM; ++k) {
        int diff = r - k; if (diff < 0) diff = -diff;
        float scale = 1.0f / (float)(diff + 1);
        acc = fmaf(sw[k * EMB_DIM + d], scale, acc);
    }
    g_table[r * EMB_DIM + d] = acc;
}

// ---------------------------------------------------------------------------
// Kernel 2: warp-cooperative output streaming.
// Per warp-iteration: lane i computes bucket index of row (base+i) — one
// index computation per ROW (was: per float4, 16x redundant). Then 16
// unrolled steps: shfl the two indices for a row pair, LDS.128 the table
// slice, STG.128 512B coalesced. Stores are independent -> deep MLP.
// ---------------------------------------------------------------------------
__global__ void __launch_bounds__(256)
embed_kernel(const float* __restrict__ x,
             const float* __restrict__ low,   // [64]; bins = low[1..63]
             float4* __restrict__ out,
             int n_rows)                       // B*F rows (multiple of 32)
{
    __shared__ float4 sT[KDIM * (EMB_DIM / 4)];   // 16 KB table
    __shared__ float  sb[NUM_BINS];               // bin boundaries

    const float4* gT4 = reinterpret_cast<const float4*>(g_table);
#pragma unroll
    for (int i = threadIdx.x; i < KDIM * (EMB_DIM / 4); i += 256)
        sT[i] = gT4[i];
    if (threadIdx.x < NUM_BINS)
        sb[threadIdx.x] = low[threadIdx.x + 1];
    __syncthreads();

    const int lane = threadIdx.x & 31;
    const int warp = threadIdx.x >> 5;
    const int half = lane >> 4;        // 0: first row of pair, 1: second
    const int part = lane & 15;        // float4 slot within a 64-float row

    const int gwarp  = blockIdx.x * 8 + warp;        // global warp id
    const int nwarps = gridDim.x * 8;

    for (int base = gwarp * 32; base < n_rows; base += nwarps * 32) {
        // --- one bucket index per row (lane i -> row base+i) ---
        const float xv = __ldg(x + base + lane);
        // index = #{ j : bins[j] < x }. Arithmetic guess (bins ~ linspace
        // step 0.1), then EXACT fixup against real bin values.
        int g = (int)floorf((xv + 3.1f) * 10.0f) + 1;
        g = max(0, min(NUM_BINS, g));
        while (g > 0 && !(xv > sb[g - 1])) --g;
        while (g < NUM_BINS && (xv > sb[g])) ++g;

        // --- fan out: 16 row-pairs, 512B coalesced store each ---
#pragma unroll
        for (int j = 0; j < 16; ++j) {
            const int idx = __shfl_sync(0xffffffffu, g, 2 * j + half);
            const float4 v = sT[(idx << 4) + part];
            __stcs(&out[(base + 2 * j) * 16 + lane], v);
        }
    }
}

extern "C" void kernel_launch(void* const* d_in, const int* in_sizes, int n_in,
                              void* d_out, int out_size) {
    const float* x      = (const float*)d_in[0];   // [B*F]
    const float* low    = (const float*)d_in[1];   // [64]
    // d_in[2] = high [64] (redundant with low for the bucket computation)
    const float* weight = (const float*)d_in[3];   // [64*64]

    float4* out = (float4*)d_out;
    const int n_rows = out_size / EMB_DIM;         // 524288

    build_table_kernel<<<16, 256>>>(weight);

    // 1024 blocks x 8 warps x 32 rows = 262144 rows/iter -> exactly 2 iters.
    int blocks = 1024;
    int max_blocks = (n_rows + 255) / 256;
    if (blocks > max_blocks) blocks = max_blocks;
    embed_kernel<<<blocks, 256>>>(x, low, out, n_rows);
}

// round 3
// speedup vs baseline: 1.3279x; 1.0479x over previous
#include <cuda_runtime.h>
#include <cuda_bf16.h>

// ContinuousEmbedding: out[b,f,:] = sum_k weight[k,:] / (|idx(x[b,f]) - k| + 1)
// Collapses to a 64x64 lookup table T (16 KB) indexed by bucket index.
//
// R3: no shared-memory table — gather straight from g_table through L1
// (16 KB fits; L1 persists within the launch). 2048 stateless blocks,
// exactly one 32-row tile per warp. PDL overlaps table build with the
// bucket-index computation of the embed kernel.

#define NUM_BINS 63
#define KDIM 64          // NUM_BINS + 1
#define EMB_DIM 64

__device__ float g_table[KDIM * EMB_DIM];   // scratch (allocation-free rule)

// ---------------------------------------------------------------------------
// Kernel 1: T[i][d] = sum_k weight[k][d] * (1/(|i-k|+1)).  <<<16, 256>>>
// Fires programmatic-launch completion so embed can start early.
// ---------------------------------------------------------------------------
__global__ void __launch_bounds__(256)
build_table_kernel(const float* __restrict__ weight) {
    __shared__ float sw[KDIM * EMB_DIM];          // 16 KB
    float4* sw4 = reinterpret_cast<float4*>(sw);
    const float4* w4 = reinterpret_cast<const float4*>(weight);
#pragma unroll
    for (int i = threadIdx.x; i < KDIM * EMB_DIM / 4; i += 256)
        sw4[i] = w4[i];
    __syncthreads();

    const int r = blockIdx.x * 4 + (threadIdx.x >> 6);  // table row 0..63
    const int d = threadIdx.x & 63;                     // emb dim 0..63
    float acc = 0.0f;
#pragma unroll
    for (int k = 0; k < KDIM; ++k) {
        int diff = r - k; if (diff < 0) diff = -diff;
        acc = fmaf(sw[k * EMB_DIM + d], 1.0f / (float)(diff + 1), acc);
    }
    g_table[r * EMB_DIM + d] = acc;

#if __CUDA_ARCH__ >= 900
    cudaTriggerProgrammaticLaunchCompletion();
#endif
}

// ---------------------------------------------------------------------------
// Kernel 2: one 32-row tile per warp. Lane i computes the bucket index of
// row base+i (one computation per ROW); then 16 unrolled steps of
// shfl -> LDG.128 (table via L1) -> STG.128 (512B coalesced, streaming).
// ---------------------------------------------------------------------------
__global__ void __launch_bounds__(256, 8)
embed_kernel(const float* __restrict__ x,
             const float* __restrict__ low,     // [64]; low[0]=-inf, bins=low[1..]
             const float4* __restrict__ table,  // g_table viewed as float4
             float4* __restrict__ out,
             int n_rows)
{
    const int lane = threadIdx.x & 31;
    const int warp = threadIdx.x >> 5;
    const int base = (blockIdx.x * 8 + warp) * 32;
    if (base >= n_rows) {
#if __CUDA_ARCH__ >= 900
        cudaGridDependencySynchronize();
#endif
        return;
    }

    // --- bucket index: g = #{ j : bins[j] < x } ---------------------------
    // Arithmetic guess (bins ~ linspace(-3.1,3.1,63), step 0.1), then EXACT
    // fixup against the real bin values so boundaries match the reference.
    const float xv = __ldg(x + base + lane);
    int g = (int)floorf((xv + 3.1f) * 10.0f) + 1;
    g = max(0, min(NUM_BINS, g));
    while (g > 0 && !(xv > __ldg(low + g))) --g;          // bins[g-1] == low[g]
    while (g < NUM_BINS && (xv > __ldg(low + g + 1))) ++g;

#if __CUDA_ARCH__ >= 900
    cudaGridDependencySynchronize();   // table must be ready past this point
#endif

    // --- fan out: 16 row-pairs, 512B coalesced streaming store each -------
    const int half = lane >> 4;        // 0: first row of pair, 1: second
    const int part = lane & 15;        // float4 slot within a 64-float row
#pragma unroll
    for (int j = 0; j < 16; ++j) {
        const int idx = __shfl_sync(0xffffffffu, g, 2 * j + half);
        const float4 v = __ldg(&table[(idx << 4) + part]);
        __stcs(&out[(base + 2 * j) * 16 + lane], v);
    }
}

extern "C" void kernel_launch(void* const* d_in, const int* in_sizes, int n_in,
                              void* d_out, int out_size) {
    const float* x      = (const float*)d_in[0];   // [B*F]
    const float* low    = (const float*)d_in[1];   // [64]
    // d_in[2] = high [64] (redundant with low for the bucket computation)
    const float* weight = (const float*)d_in[3];   // [64*64]

    float4* out = (float4*)d_out;
    const int n_rows = out_size / EMB_DIM;         // 524288

    build_table_kernel<<<16, 256>>>(weight);

    // 2048 blocks x 8 warps x 32 rows = 524288 rows exactly.
    int blocks = (n_rows + 255) / 256;             // 2048 for the real shape

    float4* table4;
    cudaGetSymbolAddress((void**)&table4, g_table); // host-side query, capture-safe? no:
    // NOTE: cudaGetSymbolAddress is NOT a kernel launch but it is legal during
    // capture (pure address query, no stream work). Still, to be safe we
    // resolve it via a device-visible cast instead if needed.

    cudaLaunchConfig_t cfg = {};
    cfg.gridDim  = dim3((unsigned)blocks, 1, 1);
    cfg.blockDim = dim3(256, 1, 1);
    cfg.dynamicSmemBytes = 0;
    cfg.stream = 0;
    cudaLaunchAttribute attr[1];
    attr[0].id = cudaLaunchAttributeProgrammaticStreamSerialization;
    attr[0].val.programmaticStreamSerializationAllowed = 1;
    cfg.attrs = attr;
    cfg.numAttrs = 1;

    cudaError_t e = cudaLaunchKernelEx(&cfg, embed_kernel,
                                       x, low, (const float4*)table4, out, n_rows);
    if (e != cudaSuccess) {
        // Fallback: plain launch (no PDL) — keeps correctness if PDL path
        // is rejected during capture on this driver.
        embed_kernel<<<blocks, 256>>>(x, low, (const float4*)table4, out, n_rows);
    }
}